// round 9
// baseline (speedup 1.0000x reference)
#include <cuda_runtime.h>
#include <cuda_bf16.h>
#include <math.h>

#define MAX_E 640000
#define MAX_N 50000
#define VDIM  128
#define CAP   128   // per-segment capacity (deg ~ Poisson(12.8), max ~45)

// -------- scratch (device globals: allocations forbidden) --------
__device__ float g_keys_proj[MAX_N * VDIM];
__device__ float g_probs[MAX_E];
__device__ float g_d[MAX_N];
__device__ int   g_cursor[MAX_N];
__device__ int   g_edge_slots[MAX_N * CAP];

// -------- kernel 0: zero cursors --------
__global__ void zero_cursor_kernel(int n) {
    int i = blockIdx.x * blockDim.x + threadIdx.x;
    if (i < n) g_cursor[i] = 0;
}

// -------- kernel 1: bucket edges by segment --------
__global__ __launch_bounds__(256)
void fill_kernel(const int* __restrict__ indices, int E) {
    int e = blockIdx.x * blockDim.x + threadIdx.x;
    if (e >= E) return;
    int n = indices[e];
    int slot = atomicAdd(&g_cursor[n], 1);
    if (slot < CAP) g_edge_slots[n * CAP + slot] = e;
}

// -------- kernel 2: tensor-core split-bf16 GEMM --------
// keys_proj[n][v] = sum_k A[n][k] * W[v][k] + b[v]
// A = A_hi + A_lo (bf16 each), W = W_hi + W_lo; D = Ah*Wh + Ah*Wl + Al*Wh
// (residual Al*Wl ~ 4e-6 relative: negligible). fp32 accumulate in HMMA.
#define GEMM_ROWS 128          // rows per block
#define LDS_PAD   132          // bf16 row stride (pad 4 -> conflict-free)
#define GEMM_SMEM (4 * 128 * LDS_PAD * 2 + 128 * 4)

__device__ __forceinline__ void mma_bf16(float* c, const unsigned* a,
                                         unsigned b0, unsigned b1) {
    asm volatile(
        "mma.sync.aligned.m16n8k16.row.col.f32.bf16.bf16.f32 "
        "{%0,%1,%2,%3}, {%4,%5,%6,%7}, {%8,%9}, {%0,%1,%2,%3};"
        : "+f"(c[0]), "+f"(c[1]), "+f"(c[2]), "+f"(c[3])
        : "r"(a[0]), "r"(a[1]), "r"(a[2]), "r"(a[3]), "r"(b0), "r"(b1));
}

__device__ __forceinline__ void split_store(__nv_bfloat16* hi, __nv_bfloat16* lo,
                                            int off, float x, float y) {
    __nv_bfloat16 hx = __float2bfloat16(x);
    __nv_bfloat16 hy = __float2bfloat16(y);
    __nv_bfloat16 lx = __float2bfloat16(x - __bfloat162float(hx));
    __nv_bfloat16 ly = __float2bfloat16(y - __bfloat162float(hy));
    *(__nv_bfloat162*)(hi + off) = __nv_bfloat162(hx, hy);
    *(__nv_bfloat162*)(lo + off) = __nv_bfloat162(lx, ly);
}

__global__ __launch_bounds__(256)
void gemm_tc_kernel(const float* __restrict__ A,     // [N,128] attn_keys
                    const float* __restrict__ W,     // [128,128] row=v
                    const float* __restrict__ bias,
                    int N) {
    extern __shared__ __align__(16) char smem_raw[];
    __nv_bfloat16* A_hi = (__nv_bfloat16*)smem_raw;        // [128][132]
    __nv_bfloat16* A_lo = A_hi + 128 * LDS_PAD;
    __nv_bfloat16* W_hi = A_lo + 128 * LDS_PAD;
    __nv_bfloat16* W_lo = W_hi + 128 * LDS_PAD;
    float* sbias = (float*)(W_lo + 128 * LDS_PAD);

    const int t = threadIdx.x;
    const int block_row = blockIdx.x * GEMM_ROWS;

    // Load + split W (128x128 f32, L2-hot) and A tile.
    for (int i = t; i < 128 * 32; i += 256) {
        int row = i >> 5, c4 = i & 31;
        float4 w = ((const float4*)W)[row * 32 + c4];
        int off = row * LDS_PAD + c4 * 4;
        split_store(W_hi, W_lo, off,     w.x, w.y);
        split_store(W_hi, W_lo, off + 2, w.z, w.w);
    }
    for (int i = t; i < 128 * 32; i += 256) {
        int row = i >> 5, c4 = i & 31;
        int grow = block_row + row;
        float4 a = make_float4(0.f, 0.f, 0.f, 0.f);
        if (grow < N) a = ((const float4*)A)[(size_t)grow * 32 + c4];
        int off = row * LDS_PAD + c4 * 4;
        split_store(A_hi, A_lo, off,     a.x, a.y);
        split_store(A_hi, A_lo, off + 2, a.z, a.w);
    }
    if (t < 128) sbias[t] = bias[t];
    __syncthreads();

    const int warp = t >> 5;
    const int lane = t & 31;
    const int g = lane >> 2;        // group id 0..7
    const int q = lane & 3;         // quad pos 0..3

    float acc[16][4];
    #pragma unroll
    for (int j = 0; j < 16; j++)
        #pragma unroll
        for (int i = 0; i < 4; i++) acc[j][i] = 0.f;

    const int r0 = warp * 16 + g;

    #pragma unroll
    for (int kk = 0; kk < 8; kk++) {
        int k0 = kk * 16;
        unsigned ah[4], al[4];
        ah[0] = *(const unsigned*)&A_hi[ r0      * LDS_PAD + k0     + q * 2];
        ah[1] = *(const unsigned*)&A_hi[(r0 + 8) * LDS_PAD + k0     + q * 2];
        ah[2] = *(const unsigned*)&A_hi[ r0      * LDS_PAD + k0 + 8 + q * 2];
        ah[3] = *(const unsigned*)&A_hi[(r0 + 8) * LDS_PAD + k0 + 8 + q * 2];
        al[0] = *(const unsigned*)&A_lo[ r0      * LDS_PAD + k0     + q * 2];
        al[1] = *(const unsigned*)&A_lo[(r0 + 8) * LDS_PAD + k0     + q * 2];
        al[2] = *(const unsigned*)&A_lo[ r0      * LDS_PAD + k0 + 8 + q * 2];
        al[3] = *(const unsigned*)&A_lo[(r0 + 8) * LDS_PAD + k0 + 8 + q * 2];

        #pragma unroll
        for (int j = 0; j < 16; j++) {
            int v = j * 8 + g;       // B col = output col group
            unsigned bh0 = *(const unsigned*)&W_hi[v * LDS_PAD + k0     + q * 2];
            unsigned bh1 = *(const unsigned*)&W_hi[v * LDS_PAD + k0 + 8 + q * 2];
            unsigned bl0 = *(const unsigned*)&W_lo[v * LDS_PAD + k0     + q * 2];
            unsigned bl1 = *(const unsigned*)&W_lo[v * LDS_PAD + k0 + 8 + q * 2];
            mma_bf16(acc[j], ah, bh0, bh1);
            mma_bf16(acc[j], ah, bl0, bl1);
            mma_bf16(acc[j], al, bh0, bh1);
        }
    }

    // Epilogue: bias + store.
    int grow0 = block_row + warp * 16 + g;
    #pragma unroll
    for (int j = 0; j < 16; j++) {
        int col = j * 8 + q * 2;
        float b0 = sbias[col], b1 = sbias[col + 1];
        if (grow0 < N) {
            *(float2*)&g_keys_proj[(size_t)grow0 * VDIM + col] =
                make_float2(acc[j][0] + b0, acc[j][1] + b1);
        }
        if (grow0 + 8 < N) {
            *(float2*)&g_keys_proj[(size_t)(grow0 + 8) * VDIM + col] =
                make_float2(acc[j][2] + b0, acc[j][3] + b1);
        }
    }
}

// -------- kernel 3: warp-per-segment, simple loop + no-max softmax --------
__global__ __launch_bounds__(256)
void segment_kernel(const float4* __restrict__ sv,
                    float* __restrict__ attn_out,
                    int N) {
    const unsigned FULL = 0xffffffffu;
    int n = (blockIdx.x * blockDim.x + threadIdx.x) >> 5;
    int lane = threadIdx.x & 31;
    if (n >= N) return;

    int deg = g_cursor[n];
    if (deg > CAP) deg = CAP;

    const float4* kp = (const float4*)g_keys_proj;
    float4 b = kp[(size_t)n * 32 + lane];

    int eids[4];
    #pragma unroll
    for (int t = 0; t < 4; t++) {
        int j = t * 32 + lane;
        eids[t] = (j < deg) ? g_edge_slots[n * CAP + j] : 0;
    }

    float d = 0.f;
    float4 acc = make_float4(0.f, 0.f, 0.f, 0.f);

    int e_next = __shfl_sync(FULL, eids[0], 0);
    float4 a_next = make_float4(0.f, 0.f, 0.f, 0.f);
    if (deg > 0) a_next = sv[(size_t)e_next * 32 + lane];

    for (int j = 0; j < deg; j++) {
        float4 a = a_next;
        int e = e_next;
        int jj = j + 1;
        if (jj < deg) {
            e_next = __shfl_sync(FULL, eids[jj >> 5], jj & 31);
            a_next = sv[(size_t)e_next * 32 + lane];
        }

        float p = fmaf(a.x, b.x, fmaf(a.y, b.y, fmaf(a.z, b.z, a.w * b.w)));
        #pragma unroll
        for (int o = 16; o > 0; o >>= 1) p += __shfl_xor_sync(FULL, p, o);

        if (lane == 0) g_probs[e] = p;

        float w = __expf(p);
        d += w;
        acc.x = fmaf(a.x, w, acc.x);
        acc.y = fmaf(a.y, w, acc.y);
        acc.z = fmaf(a.z, w, acc.z);
        acc.w = fmaf(a.w, w, acc.w);
    }

    float inv = (deg > 0) ? __fdividef(1.0f, d) : 0.0f;
    ((float4*)attn_out)[(size_t)n * 32 + lane] =
        make_float4(acc.x * inv, acc.y * inv, acc.z * inv, acc.w * inv);
    if (lane == 0) g_d[n] = d;
}

// -------- kernel 4: scores[e] = exp(p[e]) / d[n] --------
__global__ __launch_bounds__(256)
void scores_kernel(const int* __restrict__ indices,
                   float* __restrict__ scores_out,
                   int E) {
    int e = blockIdx.x * blockDim.x + threadIdx.x;
    if (e >= E) return;
    int n = __ldg(&indices[e]);
    scores_out[e] = __fdividef(__expf(g_probs[e]), g_d[n]);
}

extern "C" void kernel_launch(void* const* d_in, const int* in_sizes, int n_in,
                              void* d_out, int out_size) {
    const float* sv      = (const float*)d_in[0];
    const int*   indices = (const int*)d_in[1];
    const float* akeys   = (const float*)d_in[2];
    const float* W       = (const float*)d_in[3];
    const float* bias    = (const float*)d_in[4];

    int E = in_sizes[1];
    int N = in_sizes[2] / VDIM;

    float* scores_out = (float*)d_out;
    float* attn_out   = (float*)d_out + E;

    zero_cursor_kernel<<<(N + 255) / 256, 256>>>(N);
    fill_kernel<<<(E + 255) / 256, 256>>>(indices, E);

    cudaFuncSetAttribute(gemm_tc_kernel,
                         cudaFuncAttributeMaxDynamicSharedMemorySize, GEMM_SMEM);
    gemm_tc_kernel<<<(N + GEMM_ROWS - 1) / GEMM_ROWS, 256, GEMM_SMEM>>>(
        akeys, W, bias, N);

    segment_kernel<<<(N * 32 + 255) / 256, 256>>>((const float4*)sv, attn_out, N);

    scores_kernel<<<(E + 255) / 256, 256>>>(indices, scores_out, E);
}

// round 10
// speedup vs baseline: 1.5395x; 1.5395x over previous
#include <cuda_runtime.h>
#include <cuda_bf16.h>
#include <math.h>

#define MAX_E 640000
#define MAX_N 50000
#define VDIM  128
#define CAP   128   // per-segment capacity (deg ~ Poisson(12.8), max ~45)

// -------- scratch (device globals: allocations forbidden) --------
__device__ float         g_keys_proj[MAX_N * VDIM];
__device__ float         g_probs[MAX_E];
__device__ float         g_d[MAX_N];
__device__ int           g_cursor[MAX_N];
__device__ int           g_edge_slots[MAX_N * CAP];
__device__ __nv_bfloat16 g_Whi[VDIM * VDIM];   // pre-split W (hi)
__device__ __nv_bfloat16 g_Wlo[VDIM * VDIM];   // pre-split W (lo residual)

// -------- kernel 0: zero cursors --------
__global__ void zero_cursor_kernel(int n) {
    int i = blockIdx.x * blockDim.x + threadIdx.x;
    if (i < n) g_cursor[i] = 0;
}

// -------- kernel 1: bucket edges by segment --------
__global__ __launch_bounds__(256)
void fill_kernel(const int* __restrict__ indices, int E) {
    int e = blockIdx.x * blockDim.x + threadIdx.x;
    if (e >= E) return;
    int n = indices[e];
    int slot = atomicAdd(&g_cursor[n], 1);
    if (slot < CAP) g_edge_slots[n * CAP + slot] = e;
}

// -------- kernel 1b: split W into bf16 hi/lo (once, 16K elements) --------
__global__ __launch_bounds__(256)
void splitW_kernel(const float* __restrict__ W) {
    int i = blockIdx.x * blockDim.x + threadIdx.x;
    if (i >= VDIM * VDIM) return;
    float w = W[i];
    __nv_bfloat16 h = __float2bfloat16(w);
    g_Whi[i] = h;
    g_Wlo[i] = __float2bfloat16(w - __bfloat162float(h));
}

// -------- kernel 2: tensor-core split-bf16 GEMM --------
// keys_proj[n][v] = sum_k A[n][k]*W[v][k] + b[v];  D = Ah*Wh + Ah*Wl + Al*Wh
#define GEMM_ROWS 128
#define WPAD      136   // bf16 row stride: word-stride 68 -> bank 4g+q, conflict-free
#define GEMM_SMEM (2 * 128 * WPAD * 2 + 128 * 4)

__device__ __forceinline__ void mma_bf16(float* c, const unsigned* a,
                                         unsigned b0, unsigned b1) {
    asm volatile(
        "mma.sync.aligned.m16n8k16.row.col.f32.bf16.bf16.f32 "
        "{%0,%1,%2,%3}, {%4,%5,%6,%7}, {%8,%9}, {%0,%1,%2,%3};"
        : "+f"(c[0]), "+f"(c[1]), "+f"(c[2]), "+f"(c[3])
        : "r"(a[0]), "r"(a[1]), "r"(a[2]), "r"(a[3]), "r"(b0), "r"(b1));
}

__device__ __forceinline__ unsigned pack_hi(float2 v) {
    __nv_bfloat162 h = __floats2bfloat162_rn(v.x, v.y);
    return *(unsigned*)&h;
}
__device__ __forceinline__ unsigned pack_lo(float2 v) {
    float lx = v.x - __bfloat162float(__float2bfloat16(v.x));
    float ly = v.y - __bfloat162float(__float2bfloat16(v.y));
    __nv_bfloat162 l = __floats2bfloat162_rn(lx, ly);
    return *(unsigned*)&l;
}

__global__ __launch_bounds__(256)
void gemm_tc_kernel(const float* __restrict__ A,    // [N,128] attn_keys
                    const float* __restrict__ bias,
                    int N) {
    extern __shared__ __align__(16) char smem_raw[];
    __nv_bfloat16* W_hi = (__nv_bfloat16*)smem_raw;          // [128][WPAD]
    __nv_bfloat16* W_lo = W_hi + 128 * WPAD;
    float* sbias = (float*)(W_lo + 128 * WPAD);

    const int t = threadIdx.x;
    const int block_row = blockIdx.x * GEMM_ROWS;

    // Copy pre-split W into padded smem (uint4 = 8 bf16; 272B row stride, 16B aligned)
    for (int i = t; i < 128 * 16; i += 256) {
        int row = i >> 4, c = i & 15;
        ((uint4*)(W_hi + row * WPAD))[c] = ((const uint4*)(g_Whi + row * VDIM))[c];
        ((uint4*)(W_lo + row * WPAD))[c] = ((const uint4*)(g_Wlo + row * VDIM))[c];
    }
    if (t < 128) sbias[t] = bias[t];
    __syncthreads();

    const int warp = t >> 5;
    const int lane = t & 31;
    const int g = lane >> 2;
    const int q = lane & 3;

    const int r0 = block_row + warp * 16 + g;   // A row for a0/a2
    const int r1 = r0 + 8;                      // A row for a1/a3
    const bool v0 = (r0 < N), v1 = (r1 < N);
    const float* A0 = A + (size_t)r0 * VDIM + 2 * q;
    const float* A1 = A + (size_t)r1 * VDIM + 2 * q;

    float acc[16][4];
    #pragma unroll
    for (int j = 0; j < 16; j++)
        #pragma unroll
        for (int i = 0; i < 4; i++) acc[j][i] = 0.f;

    const float2 Z = make_float2(0.f, 0.f);
    // prefetch kk = 0
    float2 c00 = v0 ? *(const float2*)(A0)     : Z;
    float2 c10 = v1 ? *(const float2*)(A1)     : Z;
    float2 c01 = v0 ? *(const float2*)(A0 + 8) : Z;
    float2 c11 = v1 ? *(const float2*)(A1 + 8) : Z;

    #pragma unroll
    for (int kk = 0; kk < 8; kk++) {
        unsigned ah[4], al[4];
        ah[0] = pack_hi(c00); al[0] = pack_lo(c00);
        ah[1] = pack_hi(c10); al[1] = pack_lo(c10);
        ah[2] = pack_hi(c01); al[2] = pack_lo(c01);
        ah[3] = pack_hi(c11); al[3] = pack_lo(c11);

        if (kk < 7) {      // prefetch next k-slab; overlaps the j loop below
            int k0 = (kk + 1) * 16;
            c00 = v0 ? *(const float2*)(A0 + k0)     : Z;
            c10 = v1 ? *(const float2*)(A1 + k0)     : Z;
            c01 = v0 ? *(const float2*)(A0 + k0 + 8) : Z;
            c11 = v1 ? *(const float2*)(A1 + k0 + 8) : Z;
        }

        int kb = kk * 16 + q * 2;
        #pragma unroll
        for (int j = 0; j < 16; j++) {
            int v = j * 8 + g;
            unsigned bh0 = *(const unsigned*)&W_hi[v * WPAD + kb];
            unsigned bh1 = *(const unsigned*)&W_hi[v * WPAD + kb + 8];
            unsigned bl0 = *(const unsigned*)&W_lo[v * WPAD + kb];
            unsigned bl1 = *(const unsigned*)&W_lo[v * WPAD + kb + 8];
            mma_bf16(acc[j], ah, bh0, bh1);
            mma_bf16(acc[j], ah, bl0, bl1);
            mma_bf16(acc[j], al, bh0, bh1);
        }
    }

    // Epilogue: bias + store.
    #pragma unroll
    for (int j = 0; j < 16; j++) {
        int col = j * 8 + q * 2;
        float b0 = sbias[col], b1 = sbias[col + 1];
        if (v0)
            *(float2*)&g_keys_proj[(size_t)r0 * VDIM + col] =
                make_float2(acc[j][0] + b0, acc[j][1] + b1);
        if (v1)
            *(float2*)&g_keys_proj[(size_t)r1 * VDIM + col] =
                make_float2(acc[j][2] + b0, acc[j][3] + b1);
    }
}

// -------- kernel 3: warp-per-segment, simple loop + no-max softmax --------
__global__ __launch_bounds__(256)
void segment_kernel(const float4* __restrict__ sv,
                    float* __restrict__ attn_out,
                    int N) {
    const unsigned FULL = 0xffffffffu;
    int n = (blockIdx.x * blockDim.x + threadIdx.x) >> 5;
    int lane = threadIdx.x & 31;
    if (n >= N) return;

    int deg = g_cursor[n];
    if (deg > CAP) deg = CAP;

    const float4* kp = (const float4*)g_keys_proj;
    float4 b = kp[(size_t)n * 32 + lane];

    int eids[4];
    #pragma unroll
    for (int t = 0; t < 4; t++) {
        int j = t * 32 + lane;
        eids[t] = (j < deg) ? g_edge_slots[n * CAP + j] : 0;
    }

    float d = 0.f;
    float4 acc = make_float4(0.f, 0.f, 0.f, 0.f);

    int e_next = __shfl_sync(FULL, eids[0], 0);
    float4 a_next = make_float4(0.f, 0.f, 0.f, 0.f);
    if (deg > 0) a_next = sv[(size_t)e_next * 32 + lane];

    for (int j = 0; j < deg; j++) {
        float4 a = a_next;
        int e = e_next;
        int jj = j + 1;
        if (jj < deg) {
            e_next = __shfl_sync(FULL, eids[jj >> 5], jj & 31);
            a_next = sv[(size_t)e_next * 32 + lane];
        }

        float p = fmaf(a.x, b.x, fmaf(a.y, b.y, fmaf(a.z, b.z, a.w * b.w)));
        #pragma unroll
        for (int o = 16; o > 0; o >>= 1) p += __shfl_xor_sync(FULL, p, o);

        if (lane == 0) g_probs[e] = p;

        float w = __expf(p);
        d += w;
        acc.x = fmaf(a.x, w, acc.x);
        acc.y = fmaf(a.y, w, acc.y);
        acc.z = fmaf(a.z, w, acc.z);
        acc.w = fmaf(a.w, w, acc.w);
    }

    float inv = (deg > 0) ? __fdividef(1.0f, d) : 0.0f;
    ((float4*)attn_out)[(size_t)n * 32 + lane] =
        make_float4(acc.x * inv, acc.y * inv, acc.z * inv, acc.w * inv);
    if (lane == 0) g_d[n] = d;
}

// -------- kernel 4: scores[e] = exp(p[e]) / d[n] --------
__global__ __launch_bounds__(256)
void scores_kernel(const int* __restrict__ indices,
                   float* __restrict__ scores_out,
                   int E) {
    int e = blockIdx.x * blockDim.x + threadIdx.x;
    if (e >= E) return;
    int n = __ldg(&indices[e]);
    scores_out[e] = __fdividef(__expf(g_probs[e]), g_d[n]);
}

extern "C" void kernel_launch(void* const* d_in, const int* in_sizes, int n_in,
                              void* d_out, int out_size) {
    const float* sv      = (const float*)d_in[0];
    const int*   indices = (const int*)d_in[1];
    const float* akeys   = (const float*)d_in[2];
    const float* W       = (const float*)d_in[3];
    const float* bias    = (const float*)d_in[4];

    int E = in_sizes[1];
    int N = in_sizes[2] / VDIM;

    float* scores_out = (float*)d_out;
    float* attn_out   = (float*)d_out + E;

    zero_cursor_kernel<<<(N + 255) / 256, 256>>>(N);
    splitW_kernel<<<(VDIM * VDIM + 255) / 256, 256>>>(W);
    fill_kernel<<<(E + 255) / 256, 256>>>(indices, E);

    cudaFuncSetAttribute(gemm_tc_kernel,
                         cudaFuncAttributeMaxDynamicSharedMemorySize, GEMM_SMEM);
    gemm_tc_kernel<<<(N + GEMM_ROWS - 1) / GEMM_ROWS, 256, GEMM_SMEM>>>(
        akeys, bias, N);

    segment_kernel<<<(N * 32 + 255) / 256, 256>>>((const float4*)sv, attn_out, N);

    scores_kernel<<<(E + 255) / 256, 256>>>(indices, scores_out, E);
}